// round 11
// baseline (speedup 1.0000x reference)
#include <cuda_runtime.h>
#include <cuda_fp16.h>
#include <math.h>

// Problem constants
#define BB 8
#define TT 2048
#define CC 1024
#define DD 64
#define MM (BB*TT)          // 16384 rows

// ---------------------------------------------------------------------------
// Global scratch, all fp16 fragment layouts (allocation-free __device__)
// A-frag (m16k16, 128 u32/tile); B-frag (k16n8, 64 u32/tile)
// ---------------------------------------------------------------------------
__device__ unsigned g_qf [MM*DD/2];   // q,  A-frag per 64-token block (scale*log2e folded)
__device__ unsigned g_kf [MM*DD/2];   // k,  B-frag: [tb][(keyTile8)(dTile4)][64]   (k=d,n=key)
__device__ unsigned g_vf [MM*DD/2];   // v,  B-frag: [tb][(dTile8)(keyTile4)][64]   (k=key,n=d)
__device__ unsigned g_hof[MM*DD/2];   // head_out, A-frag per 64-token block
__device__ unsigned g_wpef[DD*CC/2];      // Wp_eff: [nt(128)][kt(4)][64]
__device__ unsigned g_wqkvf[3*CC*DD/2];   // W q|k|v: [ktG(64)][mat*8+nt(24)][64]

// ---------------------------------------------------------------------------
// helpers
// ---------------------------------------------------------------------------
__device__ __forceinline__ unsigned f2h2(float a, float b) {
    __half2 h = __float22half2_rn(make_float2(a, b));
    return *reinterpret_cast<unsigned*>(&h);
}
__device__ __forceinline__ float ex2(float x) {
    float y; asm("ex2.approx.f32 %0, %1;" : "=f"(y) : "f"(x)); return y;
}
__device__ __forceinline__ void mma16(float* d, const unsigned* a, unsigned b0, unsigned b1) {
    asm volatile("mma.sync.aligned.m16n8k16.row.col.f32.f16.f16.f32 "
                 "{%0,%1,%2,%3},{%4,%5,%6,%7},{%8,%9},{%0,%1,%2,%3};"
                 : "+f"(d[0]), "+f"(d[1]), "+f"(d[2]), "+f"(d[3])
                 : "r"(a[0]), "r"(a[1]), "r"(a[2]), "r"(a[3]), "r"(b0), "r"(b1));
}
__device__ __forceinline__ int aswz(int L) { return L ^ (L >> 3); }
// A-frag u32 address within a 64row x 64k block (4x4 tiles of 132 u, swizzled)
__device__ __forceinline__ int a_addr(int row, int k) {    // k even
    return ((row >> 4)*4 + (k >> 4)) * 132
         + aswz(((row & 7) << 2) | ((k >> 1) & 3)) * 4
         + ((row >> 3) & 1) + (((k >> 3) & 1) << 1);
}
__device__ __forceinline__ int bf_idx(int k, int n) {      // k even
    return ((((n & 7) << 2) | ((k >> 1) & 3)) << 1) + ((k >> 3) & 1);
}
__device__ __forceinline__ void bar64(int id) {
    asm volatile("bar.sync %0, %1;" :: "r"(id), "r"(64) : "memory");
}
__device__ __forceinline__ void cpa16(unsigned saddr, const void* g) {
    asm volatile("cp.async.cg.shared.global [%0], [%1], 16;" :: "r"(saddr), "l"(g));
}
#define CP_COMMIT() asm volatile("cp.async.commit_group;" ::: "memory")
#define CP_WAIT0()  asm volatile("cp.async.wait_group 0;" ::: "memory")

// ---------------------------------------------------------------------------
// Kernel 1 (prep): Wp_eff fold + weights -> fp16 B-frag layouts (R10 version).
// ---------------------------------------------------------------------------
__global__ __launch_bounds__(256) void prep_kernel(const float* __restrict__ Wq,
                                                   const float* __restrict__ Wk,
                                                   const float* __restrict__ Wv,
                                                   const float* __restrict__ Wp) {
    int idx2 = blockIdx.x * 256 + threadIdx.x;     // 0..65535
    int pid = idx2 >> 1, hh = idx2 & 1;
    {
        int d0 = (pid >> 10) * 2, j = pid & 1023;
        float s0 = 0.f, s1 = 0.f;
#pragma unroll
        for (int h = hh*8; h < hh*8 + 8; h++) {
            s0 += Wp[(h*64 + d0    )*1024 + j];
            s1 += Wp[(h*64 + d0 + 1)*1024 + j];
        }
        s0 += __shfl_xor_sync(0xffffffffu, s0, 1);
        s1 += __shfl_xor_sync(0xffffffffu, s1, 1);
        if (!hh)
            g_wpef[(j >> 3)*256 + (d0 >> 4)*64 + bf_idx(d0, j)] = f2h2(s0, s1);
    }
    {
        const float qs = 0.03125f * 1.44269504088896f;
        int c0 = (pid >> 6) * 2, n = pid & 63;
        int ba = (c0 >> 4)*1536 + (n >> 3)*64 + bf_idx(c0, n);
        if (!hh) {
            g_wqkvf[ba]        = f2h2(Wq[c0*64 + n]*qs, Wq[(c0+1)*64 + n]*qs);
            g_wqkvf[ba + 512]  = f2h2(Wk[c0*64 + n],    Wk[(c0+1)*64 + n]);
        } else {
            g_wqkvf[ba + 1024] = f2h2(Wv[c0*64 + n],    Wv[(c0+1)*64 + n]);
        }
    }
}

// ---------------------------------------------------------------------------
// Kernel 2: fused QKV with DEPTH-2 x prefetch (2 register stages, 2x-unrolled).
// ---------------------------------------------------------------------------
__global__ __launch_bounds__(256, 2) void qkv_kernel(const float* __restrict__ x) {
    extern __shared__ unsigned smu[];
    const int t = threadIdx.x, lane = t & 31, w = t >> 5;
    const int rowBase = blockIdx.x * 64;
    const int m0t = (w & 1) * 2;
    const int ntb = (w >> 1) * 6;

    float acc[2][6][4];
#pragma unroll
    for (int mi = 0; mi < 2; mi++)
#pragma unroll
        for (int ni = 0; ni < 6; ni++)
#pragma unroll
            for (int r = 0; r < 4; r++) acc[mi][ni][r] = 0.f;

    const int arow = t >> 2, acol4 = (t & 3) * 4;
    const float* xrow = &x[(size_t)(rowBase + arow)*CC];

    float4 xr0[4], xr1[4];
#pragma unroll
    for (int q = 0; q < 4; q++) {
        xr0[q] = *(const float4*)&xrow[q*16 + acol4];          // tile 0
        xr1[q] = *(const float4*)&xrow[64 + q*16 + acol4];     // tile 1
    }
#pragma unroll
    for (int q = 0; q < 4; q++) {
        int k = q*16 + acol4;
        smu[a_addr(arow, k)]     = f2h2(xr0[q].x, xr0[q].y);
        smu[a_addr(arow, k + 2)] = f2h2(xr0[q].z, xr0[q].w);
    }
    __syncthreads();

    for (int i2 = 0; i2 < 8; i2++) {
        const int e = i2 * 2;              // even tile index
        // ---- iter A: tile e (buf0) ----
        if (e + 2 < 16) {
#pragma unroll
            for (int q = 0; q < 4; q++)
                xr0[q] = *(const float4*)&xrow[(e+2)*64 + q*16 + acol4];
        }
        {   // STS tile e+1 -> buf1
#pragma unroll
            for (int q = 0; q < 4; q++) {
                int k = q*16 + acol4;
                smu[2112 + a_addr(arow, k)]     = f2h2(xr1[q].x, xr1[q].y);
                smu[2112 + a_addr(arow, k + 2)] = f2h2(xr1[q].z, xr1[q].w);
            }
        }
        {   // mma on buf0 (tile e)
            const unsigned* As = smu;
            const int ktG = e * 4;
#pragma unroll
            for (int ks = 0; ks < 4; ks++) {
                uint4 v0 = *(const uint4*)&As[(m0t*4 + ks)*132 + aswz(lane)*4];
                uint4 v1 = *(const uint4*)&As[((m0t+1)*4 + ks)*132 + aswz(lane)*4];
                unsigned a0[4] = {v0.x, v0.y, v0.z, v0.w};
                unsigned a1[4] = {v1.x, v1.y, v1.z, v1.w};
#pragma unroll
                for (int ni = 0; ni < 6; ni++) {
                    uint2 b = *(const uint2*)&g_wqkvf[(ktG + ks)*1536 + (ntb + ni)*64 + 2*lane];
                    mma16(acc[0][ni], a0, b.x, b.y);
                    mma16(acc[1][ni], a1, b.x, b.y);
                }
            }
        }
        __syncthreads();
        // ---- iter B: tile e+1 (buf1) ----
        if (e + 3 < 16) {
#pragma unroll
            for (int q = 0; q < 4; q++)
                xr1[q] = *(const float4*)&xrow[(e+3)*64 + q*16 + acol4];
        }
        if (e + 2 < 16) {   // STS tile e+2 -> buf0
#pragma unroll
            for (int q = 0; q < 4; q++) {
                int k = q*16 + acol4;
                smu[a_addr(arow, k)]     = f2h2(xr0[q].x, xr0[q].y);
                smu[a_addr(arow, k + 2)] = f2h2(xr0[q].z, xr0[q].w);
            }
        }
        {   // mma on buf1 (tile e+1)
            const unsigned* As = smu + 2112;
            const int ktG = (e + 1) * 4;
#pragma unroll
            for (int ks = 0; ks < 4; ks++) {
                uint4 v0 = *(const uint4*)&As[(m0t*4 + ks)*132 + aswz(lane)*4];
                uint4 v1 = *(const uint4*)&As[((m0t+1)*4 + ks)*132 + aswz(lane)*4];
                unsigned a0[4] = {v0.x, v0.y, v0.z, v0.w};
                unsigned a1[4] = {v1.x, v1.y, v1.z, v1.w};
#pragma unroll
                for (int ni = 0; ni < 6; ni++) {
                    uint2 b = *(const uint2*)&g_wqkvf[(ktG + ks)*1536 + (ntb + ni)*64 + 2*lane];
                    mma16(acc[0][ni], a0, b.x, b.y);
                    mma16(acc[1][ni], a1, b.x, b.y);
                }
            }
        }
        __syncthreads();
    }

    // ---- epilogue: stage C-frags into fp16 operand layouts (unchanged) ----
    __half* vstage = (__half*)(smu + 6272);
#pragma unroll
    for (int mi = 0; mi < 2; mi++) {
#pragma unroll
        for (int ni = 0; ni < 6; ni++) {
            int row0 = (w & 1)*32 + mi*16 + (lane >> 2);
            int col0 = (ntb + ni)*8 + 2*(lane & 3);
            int mat = col0 >> 6;
            if (mat == 0) {
                smu[a_addr(row0,     col0)] = f2h2(acc[mi][ni][0], acc[mi][ni][1]);
                smu[a_addr(row0 + 8, col0)] = f2h2(acc[mi][ni][2], acc[mi][ni][3]);
            } else if (mat == 1) {
                int d = col0 - 64;
                int t0 = ((row0 >> 3)*4 + (d >> 4))*64;
                smu[4224 + t0       + bf_idx(d, row0)] = f2h2(acc[mi][ni][0], acc[mi][ni][1]);
                smu[4224 + t0 + 256 + bf_idx(d, row0)] = f2h2(acc[mi][ni][2], acc[mi][ni][3]);
            } else {
                int d = col0 - 128;
                int u0 = (d >> 3)*256 + (row0 >> 4)*64;
                vstage[(u0 + bf_idx(row0 & 63, d))*2     + (row0 & 1)] = __float2half_rn(acc[mi][ni][0]);
                vstage[(u0 + bf_idx(row0 & 63, d+1))*2   + (row0 & 1)] = __float2half_rn(acc[mi][ni][1]);
                int r8 = row0 + 8;
                int u8 = (d >> 3)*256 + (r8 >> 4)*64;
                vstage[(u8 + bf_idx(r8 & 63, d))*2   + (r8 & 1)] = __float2half_rn(acc[mi][ni][2]);
                vstage[(u8 + bf_idx(r8 & 63, d+1))*2 + (r8 & 1)] = __float2half_rn(acc[mi][ni][3]);
            }
        }
    }
    __syncthreads();

    const size_t rb = blockIdx.x;
#pragma unroll
    for (int j = 0; j < 2; j++) {
        int tile = w*2 + j;
        uint4 v = *(const uint4*)&smu[tile*132 + aswz(lane)*4];
        *(uint4*)&g_qf[rb*2048 + tile*128 + lane*4] = v;
    }
#pragma unroll
    for (int j = 0; j < 2; j++) {
        int u = t + 256*j;
        *(uint4*)&g_kf[rb*2048 + 4*u] = *(const uint4*)&smu[4224 + 4*u];
    }
#pragma unroll
    for (int j = 0; j < 2; j++) {
        int u = t + 256*j;
        *(uint4*)&g_vf[rb*2048 + 4*u] = *(const uint4*)&smu[6272 + 4*u];
    }
}

// ---------------------------------------------------------------------------
// Kernel 3: causal flash attention. 128-key KV tiles via cp.async double
// buffer; warp (mt, half) owns same-parity 64-key blocks. No-max softmax,
// register P, 1 sync per tile. Unpaired LPT grid: 256 blocks, qt descending.
// smem: K 0/4096, V 8192/12288 (u32); Ps @16384 (2112); lsh @18496 (128 f)
// ---------------------------------------------------------------------------
__global__ __launch_bounds__(256) void attn_kernel() {
    extern __shared__ unsigned smu[];
    unsigned* Ps = smu + 16384;
    float* lsh = (float*)(smu + 18496);
    float* scr = (float*)smu;

    const int t = threadIdx.x, lane = t & 31, w = t >> 5;
    const int bid = blockIdx.x;
    const int batch = bid & 7;
    const int qt = 31 - (bid >> 3);       // big q-tiles first
    const int half_id = w & 1;
    const int mt = w >> 1;
    const int rl = lane >> 2;
    const int rA = mt*16 + rl, rB = rA + 8;
    const int barid = 1 + mt;

    const size_t qrb = batch*32 + qt;
    const int nit = (qt >> 1) + 1;        // 128-key tiles

    const unsigned sbase = (unsigned)__cvta_generic_to_shared(smu);

    // Q fragments: gmem -> registers (4 k16 tiles)
    unsigned qf[4][4];
#pragma unroll
    for (int kt = 0; kt < 4; kt++) {
        uint4 v = *(const uint4*)&g_qf[qrb*2048 + (mt*4 + kt)*128 + lane*4];
        qf[kt][0] = v.x; qf[kt][1] = v.y; qf[kt][2] = v.z; qf[kt][3] = v.w;
    }

    // issue tile 0 into buf 0
    {
        size_t gb = (size_t)(batch*32)*2048 + t*4;
        unsigned kd = sbase + t*16;
        unsigned vd = sbase + 32768 + t*16;
#pragma unroll
        for (int j = 0; j < 4; j++) {
            cpa16(kd + j*4096, &g_kf[gb + j*1024]);
            cpa16(vd + j*4096, &g_vf[gb + j*1024]);
        }
        CP_COMMIT();
    }

    float lAr = 0.f, lBr = 0.f;
    float oacc[8][4];
#pragma unroll
    for (int ni = 0; ni < 8; ni++)
#pragma unroll
        for (int r = 0; r < 4; r++) oacc[ni][r] = 0.f;

    CP_WAIT0();
    __syncthreads();

    for (int it = 0; it < nit; it++) {
        const int buf = it & 1;
        const bool more = (it + 1) < nit;
        if (more) {   // issue tile it+1 into other buffer
            size_t gb = (size_t)(batch*32 + 2*(it+1))*2048 + t*4;
            unsigned kd = sbase + (buf^1)*16384 + t*16;
            unsigned vd = sbase + 32768 + (buf^1)*16384 + t*16;
#pragma unroll
            for (int j = 0; j < 4; j++) {
                cpa16(kd + j*4096, &g_kf[gb + j*1024]);
                cpa16(vd + j*4096, &g_vf[gb + j*1024]);
            }
            CP_COMMIT();
        }

        const int kb = 2*it + half_id;    // this warp's 64-key block index
        if (kb <= qt) {
            const unsigned* Kb = smu + buf*4096 + half_id*2048;
            const unsigned* Vb = smu + 8192 + buf*4096 + half_id*2048;

            // S' = Q @ K^T over warp's 64 keys
            float sacc[8][4];
#pragma unroll
            for (int ni = 0; ni < 8; ni++)
#pragma unroll
                for (int r = 0; r < 4; r++) sacc[ni][r] = 0.f;
#pragma unroll
            for (int ks = 0; ks < 4; ks++)
#pragma unroll
                for (int ni = 0; ni < 8; ni++) {
                    uint2 b = *(const uint2*)&Kb[(ni*4 + ks)*64 + 2*lane];
                    mma16(sacc[ni], qf[ks], b.x, b.y);
                }

            // causal mask on the diagonal 64-block
            if (kb == qt) {
#pragma unroll
                for (int ni = 0; ni < 8; ni++) {
                    int c0 = ni*8 + 2*(lane & 3);
                    if (c0     > rA) sacc[ni][0] = -1e30f;
                    if (c0 + 1 > rA) sacc[ni][1] = -1e30f;
                    if (c0     > rB) sacc[ni][2] = -1e30f;
                    if (c0 + 1 > rB) sacc[ni][3] = -1e30f;
                }
            }

            // P = 2^S' into A-fragment registers (4 key16 tiles)
            unsigned pa[4][4];
#pragma unroll
            for (int ni = 0; ni < 8; ni++) {
                float p0 = ex2(sacc[ni][0]);
                float p1 = ex2(sacc[ni][1]);
                float p2 = ex2(sacc[ni][2]);
                float p3 = ex2(sacc[ni][3]);
                lAr += p0 + p1;
                lBr += p2 + p3;
                pa[ni >> 1][(ni & 1)*2]     = f2h2(p0, p1);
                pa[ni >> 1][(ni & 1)*2 + 1] = f2h2(p2, p3);
            }

            // O += P @ V over warp's 64 keys, all 64 d-cols
#pragma unroll
            for (int p = 0; p < 4; p++)
#pragma unroll
                for (int ni = 0; ni < 8; ni++) {
                    uint2 b = *(const uint2*)&Vb[(ni*4 + p)*64 + 2*lane];
                    mma16(oacc[ni], pa[p], b.x, b.y);
                }
        }

        if (more) CP_WAIT0();
        __syncthreads();
    }

    // ---- reduce l across lanes, then merge the two column halves ----
    lAr += __shfl_xor_sync(0xffffffffu, lAr, 1);
    lAr += __shfl_xor_sync(0xffffffffu, lAr, 2);
    lBr += __shfl_xor_sync(0xffffffffu, lBr, 1);
    lBr += __shfl_xor_sync(0xffffffffu, lBr, 2);
    if ((lane & 3) == 0) {
        lsh[rA*2 + half_id] = lAr;
        lsh[rB*2 + half_id] = lBr;
    }
    bar64(barid);
    float iA = 1.0f / (lsh[rA*2] + lsh[rA*2 + 1]);
    float iB = 1.0f / (lsh[rB*2] + lsh[rB*2 + 1]);

    float* sc = scr + mt*1024;
    if (half_id) {
#pragma unroll
        for (int ni = 0; ni < 8; ni++) {
            sc[(ni*4 + 0)*32 + lane] = oacc[ni][0];
            sc[(ni*4 + 1)*32 + lane] = oacc[ni][1];
            sc[(ni*4 + 2)*32 + lane] = oacc[ni][2];
            sc[(ni*4 + 3)*32 + lane] = oacc[ni][3];
        }
    }
    bar64(barid);
    if (!half_id) {
#pragma unroll
        for (int ni = 0; ni < 8; ni++) {
            int d0 = ni*8 + 2*(lane & 3);
            float v0 = (oacc[ni][0] + sc[(ni*4 + 0)*32 + lane]) * iA;
            float v1 = (oacc[ni][1] + sc[(ni*4 + 1)*32 + lane]) * iA;
            float v2 = (oacc[ni][2] + sc[(ni*4 + 2)*32 + lane]) * iB;
            float v3 = (oacc[ni][3] + sc[(ni*4 + 3)*32 + lane]) * iB;
            Ps[a_addr(mt*16 + rl,     d0)] = f2h2(v0, v1);
            Ps[a_addr(mt*16 + rl + 8, d0)] = f2h2(v2, v3);
        }
    }
    __syncthreads();
#pragma unroll
    for (int j = 0; j < 2; j++) {
        int tile = w*2 + j;
        uint4 v = *(const uint4*)&Ps[tile*132 + aswz(lane)*4];
        *(uint4*)&g_hof[qrb*2048 + tile*128 + lane*4] = v;
    }
}

// ---------------------------------------------------------------------------
// Kernel 4: out = ho @ Wp_eff + bp. B slice (16 KB) smem-resident; output
// tile staged in smem -> fully coalesced STG.128. Grid (8 x 64), 4 rb each.
// smem: Bs 4096 u32 + Os 64x132 float.
// ---------------------------------------------------------------------------
__global__ __launch_bounds__(256) void proj_kernel(float* __restrict__ out,
                                                   const float* __restrict__ bp) {
    extern __shared__ unsigned psm[];
    unsigned* Bs = psm;                 // [ntLocal(16)][kt(4)][64]
    float* Os = (float*)(psm + 4096);   // 64 x 132 staging

    const int t = threadIdx.x, lane = t & 31, w = t >> 5;
    const int ntBase = blockIdx.x * 16;
    const int colBase = blockIdx.x * 128;
    const int mt = w & 3;
    const int ntb = (w >> 2) * 8;

#pragma unroll
    for (int j = 0; j < 4; j++) {
        int u = t + 256*j;
        *(uint4*)&Bs[4*u] = *(const uint4*)&g_wpef[(size_t)ntBase*256 + 4*u];
    }
    float2 bias[8];
#pragma unroll
    for (int ni = 0; ni < 8; ni++)
        bias[ni] = *(const float2*)&bp[colBase + (ntb + ni)*8 + 2*(lane & 3)];
    __syncthreads();

    const size_t rb0 = (size_t)blockIdx.y * 4;
    const int rowA = mt*16 + (lane >> 2);
    const int rowB = rowA + 8;

    uint4 a0[4];
#pragma unroll
    for (int ks = 0; ks < 4; ks++)
        a0[ks] = *(const uint4*)&g_hof[rb0*2048 + (mt*4 + ks)*128 + lane*4];

    for (int i = 0; i < 4; i++) {
        const size_t rb = rb0 + i;
        uint4 an[4];
        if (i < 3) {
#pragma unroll
            for (int ks = 0; ks < 4; ks++)
                an[ks] = *(const uint4*)&g_hof[(rb + 1)*2048 + (mt*4 + ks)*128 + lane*4];
        }

        float acc[8][4];
#pragma unroll
        for (int ni = 0; ni < 8; ni++)
#pragma unroll
            for (int r = 0; r < 4; r++) acc[ni][r] = 0.f;

#pragma unroll
        for (int ks = 0; ks < 4; ks++) {
            unsigned a[4] = {a0[ks].x, a0[ks].y, a0[ks].z, a0[ks].w};
#pragma unroll
            for (int ni = 0; ni < 8; ni++) {
                uint2 b = *(const uint2*)&Bs[((ntb + ni)*4 + ks)*64 + 2*lane];
                mma16(acc[ni], a, b.x, b.y);
            }
        }

        // stage out tile (with bias) then coalesced float4 stores
#pragma unroll
        for (int ni = 0; ni < 8; ni++) {
            int col = (ntb + ni)*8 + 2*(lane & 3);
            *(float2*)&Os[rowA*132 + col] =
                make_float2(acc[ni][0] + bias[ni].x, acc[ni][1] + bias[ni].y);
            *(float2*)&Os[rowB*132 + col] =
                make_float2(acc[ni][2] + bias[ni].x, acc[ni][3] + bias[ni].y);
        }
        __syncthreads();
#pragma unroll
        for (int j = 0; j < 8; j++) {
            int u = t + 256*j;             // 2048 float4s
            int row = u >> 5, c4 = (u & 31)*4;
            float4 v = *(const float4*)&Os[row*132 + c4];
            *(float4*)&out[(size_t)(rb*64 + row)*CC + colBase + c4] = v;
        }
        __syncthreads();
#pragma unroll
        for (int ks = 0; ks < 4; ks++) a0[ks] = an[ks];
    }
}

// ---------------------------------------------------------------------------
// Launch
// ---------------------------------------------------------------------------
extern "C" void kernel_launch(void* const* d_in, const int* in_sizes, int n_in,
                              void* d_out, int out_size) {
    const float* x  = (const float*)d_in[0];
    const float* Wq = (const float*)d_in[1];
    const float* Wk = (const float*)d_in[2];
    const float* Wv = (const float*)d_in[3];
    const float* Wp = (const float*)d_in[4];
    const float* bp = (const float*)d_in[5];
    float* out = (float*)d_out;

    const int qkv_smem  = 8320 * 4;     // 33280 B
    const int attn_smem = 18624 * 4;    // 74496 B
    const int proj_smem = (4096 + 8448) * 4;  // 50176 B

    cudaFuncSetAttribute(qkv_kernel,  cudaFuncAttributeMaxDynamicSharedMemorySize, qkv_smem);
    cudaFuncSetAttribute(attn_kernel, cudaFuncAttributeMaxDynamicSharedMemorySize, attn_smem);
    cudaFuncSetAttribute(proj_kernel, cudaFuncAttributeMaxDynamicSharedMemorySize, proj_smem);

    prep_kernel<<<256, 256>>>(Wq, Wk, Wv, Wp);
    qkv_kernel<<<MM/64, 256, qkv_smem>>>(x);
    attn_kernel<<<256, 256, attn_smem>>>();
    proj_kernel<<<dim3(8, 64), 256, proj_smem>>>(out, bp);
}

// round 12
// speedup vs baseline: 1.0980x; 1.0980x over previous
#include <cuda_runtime.h>
#include <cuda_fp16.h>
#include <math.h>

// Problem constants
#define BB 8
#define TT 2048
#define CC 1024
#define DD 64
#define MM (BB*TT)          // 16384 rows

// ---------------------------------------------------------------------------
// Global scratch, all fp16 fragment layouts (allocation-free __device__)
// A-frag (m16k16, 128 u32/tile); B-frag (k16n8, 64 u32/tile)
// ---------------------------------------------------------------------------
__device__ unsigned g_qf [MM*DD/2];   // q,  A-frag per 64-token block (scale*log2e folded)
__device__ unsigned g_kf [MM*DD/2];   // k,  B-frag: [tb][(keyTile8)(dTile4)][64]   (k=d,n=key)
__device__ unsigned g_vf [MM*DD/2];   // v,  B-frag: [tb][(dTile8)(keyTile4)][64]   (k=key,n=d)
__device__ unsigned g_hof[MM*DD/2];   // head_out, A-frag per 64-token block
__device__ unsigned g_wpef[DD*CC/2];      // Wp_eff: [nt(128)][kt(4)][64]
__device__ unsigned g_wqkvf[3*CC*DD/2];   // W q|k|v: [ktG(64)][mat*8+nt(24)][64]

// ---------------------------------------------------------------------------
// helpers
// ---------------------------------------------------------------------------
__device__ __forceinline__ unsigned f2h2(float a, float b) {
    __half2 h = __float22half2_rn(make_float2(a, b));
    return *reinterpret_cast<unsigned*>(&h);
}
__device__ __forceinline__ float ex2(float x) {
    float y; asm("ex2.approx.f32 %0, %1;" : "=f"(y) : "f"(x)); return y;
}
__device__ __forceinline__ void mma16(float* d, const unsigned* a, unsigned b0, unsigned b1) {
    asm volatile("mma.sync.aligned.m16n8k16.row.col.f32.f16.f16.f32 "
                 "{%0,%1,%2,%3},{%4,%5,%6,%7},{%8,%9},{%0,%1,%2,%3};"
                 : "+f"(d[0]), "+f"(d[1]), "+f"(d[2]), "+f"(d[3])
                 : "r"(a[0]), "r"(a[1]), "r"(a[2]), "r"(a[3]), "r"(b0), "r"(b1));
}
__device__ __forceinline__ int aswz(int L) { return L ^ (L >> 3); }
// A-frag u32 address within a 64row x 64k block (4x4 tiles of 132 u, swizzled)
__device__ __forceinline__ int a_addr(int row, int k) {    // k even
    return ((row >> 4)*4 + (k >> 4)) * 132
         + aswz(((row & 7) << 2) | ((k >> 1) & 3)) * 4
         + ((row >> 3) & 1) + (((k >> 3) & 1) << 1);
}
__device__ __forceinline__ int bf_idx(int k, int n) {      // k even
    return ((((n & 7) << 2) | ((k >> 1) & 3)) << 1) + ((k >> 3) & 1);
}
__device__ __forceinline__ void bar64(int id) {
    asm volatile("bar.sync %0, %1;" :: "r"(id), "r"(64) : "memory");
}

// ---------------------------------------------------------------------------
// Kernel 1 (prep): Wp_eff fold + weights -> fp16 B-frag layouts (R10 version).
// ---------------------------------------------------------------------------
__global__ __launch_bounds__(256) void prep_kernel(const float* __restrict__ Wq,
                                                   const float* __restrict__ Wk,
                                                   const float* __restrict__ Wv,
                                                   const float* __restrict__ Wp) {
    int idx2 = blockIdx.x * 256 + threadIdx.x;     // 0..65535
    int pid = idx2 >> 1, hh = idx2 & 1;
    {
        int d0 = (pid >> 10) * 2, j = pid & 1023;
        float s0 = 0.f, s1 = 0.f;
#pragma unroll
        for (int h = hh*8; h < hh*8 + 8; h++) {
            s0 += Wp[(h*64 + d0    )*1024 + j];
            s1 += Wp[(h*64 + d0 + 1)*1024 + j];
        }
        s0 += __shfl_xor_sync(0xffffffffu, s0, 1);
        s1 += __shfl_xor_sync(0xffffffffu, s1, 1);
        if (!hh)
            g_wpef[(j >> 3)*256 + (d0 >> 4)*64 + bf_idx(d0, j)] = f2h2(s0, s1);
    }
    {
        const float qs = 0.03125f * 1.44269504088896f;
        int c0 = (pid >> 6) * 2, n = pid & 63;
        int ba = (c0 >> 4)*1536 + (n >> 3)*64 + bf_idx(c0, n);
        if (!hh) {
            g_wqkvf[ba]        = f2h2(Wq[c0*64 + n]*qs, Wq[(c0+1)*64 + n]*qs);
            g_wqkvf[ba + 512]  = f2h2(Wk[c0*64 + n],    Wk[(c0+1)*64 + n]);
        } else {
            g_wqkvf[ba + 1024] = f2h2(Wv[c0*64 + n],    Wv[(c0+1)*64 + n]);
        }
    }
}

// ---------------------------------------------------------------------------
// Kernel 2: fused QKV with DEPTH-2 x register prefetch (the ONLY change vs
// the 78.3us R10 kernel). Two register stages, loop 2x-unrolled; sync
// structure identical (1 sync per 64-k tile).
// ---------------------------------------------------------------------------
__global__ __launch_bounds__(256, 2) void qkv_kernel(const float* __restrict__ x) {
    extern __shared__ unsigned smu[];
    const int t = threadIdx.x, lane = t & 31, w = t >> 5;
    const int rowBase = blockIdx.x * 64;
    const int m0t = (w & 1) * 2;
    const int ntb = (w >> 1) * 6;

    float acc[2][6][4];
#pragma unroll
    for (int mi = 0; mi < 2; mi++)
#pragma unroll
        for (int ni = 0; ni < 6; ni++)
#pragma unroll
            for (int r = 0; r < 4; r++) acc[mi][ni][r] = 0.f;

    const int arow = t >> 2, acol4 = (t & 3) * 4;
    const float* xrow = &x[(size_t)(rowBase + arow)*CC];

    float4 xr0[4], xr1[4];
#pragma unroll
    for (int q = 0; q < 4; q++) {
        xr0[q] = *(const float4*)&xrow[q*16 + acol4];          // tile 0
        xr1[q] = *(const float4*)&xrow[64 + q*16 + acol4];     // tile 1
    }
#pragma unroll
    for (int q = 0; q < 4; q++) {
        int k = q*16 + acol4;
        smu[a_addr(arow, k)]     = f2h2(xr0[q].x, xr0[q].y);
        smu[a_addr(arow, k + 2)] = f2h2(xr0[q].z, xr0[q].w);
    }
    __syncthreads();

    for (int i2 = 0; i2 < 8; i2++) {
        const int e = i2 * 2;              // even tile index
        // ---- iter A: compute tile e from buf0 ----
        if (e + 2 < 16) {
#pragma unroll
            for (int q = 0; q < 4; q++)
                xr0[q] = *(const float4*)&xrow[(e+2)*64 + q*16 + acol4];
        }
        {   // STS tile e+1 -> buf1
#pragma unroll
            for (int q = 0; q < 4; q++) {
                int k = q*16 + acol4;
                smu[2112 + a_addr(arow, k)]     = f2h2(xr1[q].x, xr1[q].y);
                smu[2112 + a_addr(arow, k + 2)] = f2h2(xr1[q].z, xr1[q].w);
            }
        }
        {   // mma on buf0 (tile e)
            const unsigned* As = smu;
            const int ktG = e * 4;
#pragma unroll
            for (int ks = 0; ks < 4; ks++) {
                uint4 v0 = *(const uint4*)&As[(m0t*4 + ks)*132 + aswz(lane)*4];
                uint4 v1 = *(const uint4*)&As[((m0t+1)*4 + ks)*132 + aswz(lane)*4];
                unsigned a0[4] = {v0.x, v0.y, v0.z, v0.w};
                unsigned a1[4] = {v1.x, v1.y, v1.z, v1.w};
#pragma unroll
                for (int ni = 0; ni < 6; ni++) {
                    uint2 b = *(const uint2*)&g_wqkvf[(ktG + ks)*1536 + (ntb + ni)*64 + 2*lane];
                    mma16(acc[0][ni], a0, b.x, b.y);
                    mma16(acc[1][ni], a1, b.x, b.y);
                }
            }
        }
        __syncthreads();
        // ---- iter B: compute tile e+1 from buf1 ----
        if (e + 3 < 16) {
#pragma unroll
            for (int q = 0; q < 4; q++)
                xr1[q] = *(const float4*)&xrow[(e+3)*64 + q*16 + acol4];
        }
        if (e + 2 < 16) {   // STS tile e+2 -> buf0
#pragma unroll
            for (int q = 0; q < 4; q++) {
                int k = q*16 + acol4;
                smu[a_addr(arow, k)]     = f2h2(xr0[q].x, xr0[q].y);
                smu[a_addr(arow, k + 2)] = f2h2(xr0[q].z, xr0[q].w);
            }
        }
        {   // mma on buf1 (tile e+1)
            const unsigned* As = smu + 2112;
            const int ktG = (e + 1) * 4;
#pragma unroll
            for (int ks = 0; ks < 4; ks++) {
                uint4 v0 = *(const uint4*)&As[(m0t*4 + ks)*132 + aswz(lane)*4];
                uint4 v1 = *(const uint4*)&As[((m0t+1)*4 + ks)*132 + aswz(lane)*4];
                unsigned a0[4] = {v0.x, v0.y, v0.z, v0.w};
                unsigned a1[4] = {v1.x, v1.y, v1.z, v1.w};
#pragma unroll
                for (int ni = 0; ni < 6; ni++) {
                    uint2 b = *(const uint2*)&g_wqkvf[(ktG + ks)*1536 + (ntb + ni)*64 + 2*lane];
                    mma16(acc[0][ni], a0, b.x, b.y);
                    mma16(acc[1][ni], a1, b.x, b.y);
                }
            }
        }
        __syncthreads();
    }

    // ---- epilogue: stage C-frags into fp16 operand layouts (unchanged) ----
    __half* vstage = (__half*)(smu + 6272);
#pragma unroll
    for (int mi = 0; mi < 2; mi++) {
#pragma unroll
        for (int ni = 0; ni < 6; ni++) {
            int row0 = (w & 1)*32 + mi*16 + (lane >> 2);
            int col0 = (ntb + ni)*8 + 2*(lane & 3);
            int mat = col0 >> 6;
            if (mat == 0) {
                smu[a_addr(row0,     col0)] = f2h2(acc[mi][ni][0], acc[mi][ni][1]);
                smu[a_addr(row0 + 8, col0)] = f2h2(acc[mi][ni][2], acc[mi][ni][3]);
            } else if (mat == 1) {
                int d = col0 - 64;
                int t0 = ((row0 >> 3)*4 + (d >> 4))*64;
                smu[4224 + t0       + bf_idx(d, row0)] = f2h2(acc[mi][ni][0], acc[mi][ni][1]);
                smu[4224 + t0 + 256 + bf_idx(d, row0)] = f2h2(acc[mi][ni][2], acc[mi][ni][3]);
            } else {
                int d = col0 - 128;
                int u0 = (d >> 3)*256 + (row0 >> 4)*64;
                vstage[(u0 + bf_idx(row0 & 63, d))*2     + (row0 & 1)] = __float2half_rn(acc[mi][ni][0]);
                vstage[(u0 + bf_idx(row0 & 63, d+1))*2   + (row0 & 1)] = __float2half_rn(acc[mi][ni][1]);
                int r8 = row0 + 8;
                int u8 = (d >> 3)*256 + (r8 >> 4)*64;
                vstage[(u8 + bf_idx(r8 & 63, d))*2   + (r8 & 1)] = __float2half_rn(acc[mi][ni][2]);
                vstage[(u8 + bf_idx(r8 & 63, d+1))*2 + (r8 & 1)] = __float2half_rn(acc[mi][ni][3]);
            }
        }
    }
    __syncthreads();

    const size_t rb = blockIdx.x;
#pragma unroll
    for (int j = 0; j < 2; j++) {
        int tile = w*2 + j;
        uint4 v = *(const uint4*)&smu[tile*132 + aswz(lane)*4];
        *(uint4*)&g_qf[rb*2048 + tile*128 + lane*4] = v;
    }
#pragma unroll
    for (int j = 0; j < 2; j++) {
        int u = t + 256*j;
        *(uint4*)&g_kf[rb*2048 + 4*u] = *(const uint4*)&smu[4224 + 4*u];
    }
#pragma unroll
    for (int j = 0; j < 2; j++) {
        int u = t + 256*j;
        *(uint4*)&g_vf[rb*2048 + 4*u] = *(const uint4*)&smu[6272 + 4*u];
    }
}

// ---------------------------------------------------------------------------
// Kernel 3: causal flash attention (EXACT R10 version, 78.3us baseline).
// No-max softmax, register P, deferred l reduction, 1 sync per KV tile.
// Unpaired grid: 256 blocks, one q-tile each, qt descending (LPT).
// ---------------------------------------------------------------------------
__global__ __launch_bounds__(256, 1) void attn_kernel() {
    extern __shared__ unsigned smu[];
    unsigned* Ps = smu + 8192;
    float* lsh = (float*)(smu + 10304);
    float* scr = (float*)smu;

    const int t = threadIdx.x, lane = t & 31, w = t >> 5;
    const int bid = blockIdx.x;
    const int batch = bid & 7;
    const int qt = 31 - (bid >> 3);       // big q-tiles first
    const int half_id = w & 1;
    const int mt = w >> 1;
    const int rl = lane >> 2;
    const int rA = mt*16 + rl, rB = rA + 8;
    const int colb = half_id * 32;
    const int barid = 1 + mt;

    const size_t qrb = batch*32 + qt;
    const int ntiles = qt + 1;

    unsigned qf[4][4];
#pragma unroll
    for (int kt = 0; kt < 4; kt++) {
        uint4 v = *(const uint4*)&g_qf[qrb*2048 + (mt*4 + kt)*128 + lane*4];
        qf[kt][0] = v.x; qf[kt][1] = v.y; qf[kt][2] = v.z; qf[kt][3] = v.w;
    }
    uint4 kr[2], vr[2];
    {
        size_t tb = batch*32;
#pragma unroll
        for (int j = 0; j < 2; j++) {
            kr[j] = *(const uint4*)&g_kf[tb*2048 + 4*(t + 256*j)];
            vr[j] = *(const uint4*)&g_vf[tb*2048 + 4*(t + 256*j)];
        }
    }
#pragma unroll
    for (int j = 0; j < 2; j++) {
        *(uint4*)&smu[4*(t + 256*j)]        = kr[j];
        *(uint4*)&smu[4096 + 4*(t + 256*j)] = vr[j];
    }

    float lAr = 0.f, lBr = 0.f;
    float oacc[8][4];
#pragma unroll
    for (int ni = 0; ni < 8; ni++)
#pragma unroll
        for (int r = 0; r < 4; r++) oacc[ni][r] = 0.f;
    __syncthreads();

    for (int it = 0; it < ntiles; it++) {
        const unsigned* Kb = smu + (it & 1)*2048;
        const unsigned* Vb = smu + 4096 + (it & 1)*2048;

        float sacc[4][4];
#pragma unroll
        for (int ni = 0; ni < 4; ni++)
#pragma unroll
            for (int r = 0; r < 4; r++) sacc[ni][r] = 0.f;
#pragma unroll
        for (int ks = 0; ks < 4; ks++)
#pragma unroll
            for (int ni = 0; ni < 4; ni++) {
                uint2 b = *(const uint2*)&Kb[((half_id*4 + ni)*4 + ks)*64 + 2*lane];
                mma16(sacc[ni], qf[ks], b.x, b.y);
            }

        const bool more = (it + 1) < ntiles;
        if (more) {
            size_t tb = batch*32 + it + 1;
#pragma unroll
            for (int j = 0; j < 2; j++) {
                kr[j] = *(const uint4*)&g_kf[tb*2048 + 4*(t + 256*j)];
                vr[j] = *(const uint4*)&g_vf[tb*2048 + 4*(t + 256*j)];
            }
        }

        if (it == ntiles - 1) {
#pragma unroll
            for (int ni = 0; ni < 4; ni++) {
                int c0 = colb + ni*8 + 2*(lane & 3);
                if (c0     > rA) sacc[ni][0] = -1e30f;
                if (c0 + 1 > rA) sacc[ni][1] = -1e30f;
                if (c0     > rB) sacc[ni][2] = -1e30f;
                if (c0 + 1 > rB) sacc[ni][3] = -1e30f;
            }
        }

        unsigned pa[2][4];
#pragma unroll
        for (int ni = 0; ni < 4; ni++) {
            float p0 = ex2(sacc[ni][0]);
            float p1 = ex2(sacc[ni][1]);
            float p2 = ex2(sacc[ni][2]);
            float p3 = ex2(sacc[ni][3]);
            lAr += p0 + p1;
            lBr += p2 + p3;
            pa[ni >> 1][(ni & 1)*2]     = f2h2(p0, p1);
            pa[ni >> 1][(ni & 1)*2 + 1] = f2h2(p2, p3);
        }

#pragma unroll
        for (int p = 0; p < 2; p++)
#pragma unroll
            for (int ni = 0; ni < 8; ni++) {
                uint2 b = *(const uint2*)&Vb[(ni*4 + half_id*2 + p)*64 + 2*lane];
                mma16(oacc[ni], pa[p], b.x, b.y);
            }

        if (more) {
            unsigned nb = ((it + 1) & 1) * 2048;
#pragma unroll
            for (int j = 0; j < 2; j++) {
                *(uint4*)&smu[nb + 4*(t + 256*j)]        = kr[j];
                *(uint4*)&smu[4096 + nb + 4*(t + 256*j)] = vr[j];
            }
        }
        __syncthreads();
    }

    lAr += __shfl_xor_sync(0xffffffffu, lAr, 1);
    lAr += __shfl_xor_sync(0xffffffffu, lAr, 2);
    lBr += __shfl_xor_sync(0xffffffffu, lBr, 1);
    lBr += __shfl_xor_sync(0xffffffffu, lBr, 2);
    if ((lane & 3) == 0) {
        lsh[rA*2 + half_id] = lAr;
        lsh[rB*2 + half_id] = lBr;
    }
    bar64(barid);
    float iA = 1.0f / (lsh[rA*2] + lsh[rA*2 + 1]);
    float iB = 1.0f / (lsh[rB*2] + lsh[rB*2 + 1]);

    float* sc = scr + mt*1024;
    if (half_id) {
#pragma unroll
        for (int ni = 0; ni < 8; ni++) {
            sc[(ni*4 + 0)*32 + lane] = oacc[ni][0];
            sc[(ni*4 + 1)*32 + lane] = oacc[ni][1];
            sc[(ni*4 + 2)*32 + lane] = oacc[ni][2];
            sc[(ni*4 + 3)*32 + lane] = oacc[ni][3];
        }
    }
    bar64(barid);
    if (!half_id) {
#pragma unroll
        for (int ni = 0; ni < 8; ni++) {
            int d0 = ni*8 + 2*(lane & 3);
            float v0 = (oacc[ni][0] + sc[(ni*4 + 0)*32 + lane]) * iA;
            float v1 = (oacc[ni][1] + sc[(ni*4 + 1)*32 + lane]) * iA;
            float v2 = (oacc[ni][2] + sc[(ni*4 + 2)*32 + lane]) * iB;
            float v3 = (oacc[ni][3] + sc[(ni*4 + 3)*32 + lane]) * iB;
            Ps[a_addr(mt*16 + rl,     d0)] = f2h2(v0, v1);
            Ps[a_addr(mt*16 + rl + 8, d0)] = f2h2(v2, v3);
        }
    }
    __syncthreads();
#pragma unroll
    for (int j = 0; j < 2; j++) {
        int tile = w*2 + j;
        uint4 v = *(const uint4*)&Ps[tile*132 + aswz(lane)*4];
        *(uint4*)&g_hof[qrb*2048 + tile*128 + lane*4] = v;
    }
}

// ---------------------------------------------------------------------------
// Kernel 4: out = ho @ Wp_eff + bp (EXACT R10 version, 78.3us baseline).
// B slice (16 KB) resident in smem; 4 row-blocks per block with A prefetch.
// Grid (8 colblocks x 64 rowgroups) = 512 blocks.
// ---------------------------------------------------------------------------
__global__ __launch_bounds__(256) void proj_kernel(float* __restrict__ out,
                                                   const float* __restrict__ bp) {
    __shared__ unsigned Bs[4096];       // [ntLocal(16)][kt(4)][64]

    const int t = threadIdx.x, lane = t & 31, w = t >> 5;
    const int ntBase = blockIdx.x * 16;
    const int colBase = blockIdx.x * 128;
    const int mt = w & 3;
    const int ntb = (w >> 2) * 8;

#pragma unroll
    for (int j = 0; j < 4; j++) {
        int u = t + 256*j;              // 0..1023 (x4 u32)
        *(uint4*)&Bs[4*u] = *(const uint4*)&g_wpef[(size_t)ntBase*256 + 4*u];
    }
    float2 bias[8];
#pragma unroll
    for (int ni = 0; ni < 8; ni++)
        bias[ni] = *(const float2*)&bp[colBase + (ntb + ni)*8 + 2*(lane & 3)];
    __syncthreads();

    const size_t rb0 = (size_t)blockIdx.y * 4;
    uint4 a0[4];
#pragma unroll
    for (int ks = 0; ks < 4; ks++)
        a0[ks] = *(const uint4*)&g_hof[rb0*2048 + (mt*4 + ks)*128 + lane*4];

    for (int i = 0; i < 4; i++) {
        const size_t rb = rb0 + i;
        uint4 an[4];
        if (i < 3) {
#pragma unroll
            for (int ks = 0; ks < 4; ks++)
                an[ks] = *(const uint4*)&g_hof[(rb + 1)*2048 + (mt*4 + ks)*128 + lane*4];
        }

        float acc[8][4];
#pragma unroll
        for (int ni = 0; ni < 8; ni++)
#pragma unroll
            for (int r = 0; r < 4; r++) acc[ni][r] = 0.f;

#pragma unroll
        for (int ks = 0; ks < 4; ks++) {
            unsigned a[4] = {a0[ks].x, a0[ks].y, a0[ks].z, a0[ks].w};
#pragma unroll
            for (int ni = 0; ni < 8; ni++) {
                uint2 b = *(const uint2*)&Bs[((ntb + ni)*4 + ks)*64 + 2*lane];
                mma16(acc[ni], a, b.x, b.y);
            }
        }

        int row = (int)rb*64 + mt*16 + (lane >> 2);
#pragma unroll
        for (int ni = 0; ni < 8; ni++) {
            int col = colBase + (ntb + ni)*8 + 2*(lane & 3);
            *(float2*)&out[(size_t)row*CC + col] =
                make_float2(acc[ni][0] + bias[ni].x, acc[ni][1] + bias[ni].y);
            *(float2*)&out[(size_t)(row + 8)*CC + col] =
                make_float2(acc[ni][2] + bias[ni].x, acc[ni][3] + bias[ni].y);
        }
#pragma unroll
        for (int ks = 0; ks < 4; ks++) a0[ks] = an[ks];
    }
}

// ---------------------------------------------------------------------------
// Launch
// ---------------------------------------------------------------------------
extern "C" void kernel_launch(void* const* d_in, const int* in_sizes, int n_in,
                              void* d_out, int out_size) {
    const float* x  = (const float*)d_in[0];
    const float* Wq = (const float*)d_in[1];
    const float* Wk = (const float*)d_in[2];
    const float* Wv = (const float*)d_in[3];
    const float* Wp = (const float*)d_in[4];
    const float* bp = (const float*)d_in[5];
    float* out = (float*)d_out;

    const int qkv_smem  = 8320 * 4;    // 33280 B
    const int attn_smem = 10432 * 4;   // 41728 B

    cudaFuncSetAttribute(qkv_kernel,  cudaFuncAttributeMaxDynamicSharedMemorySize, qkv_smem);
    cudaFuncSetAttribute(attn_kernel, cudaFuncAttributeMaxDynamicSharedMemorySize, attn_smem);

    prep_kernel<<<256, 256>>>(Wq, Wk, Wv, Wp);
    qkv_kernel<<<MM/64, 256, qkv_smem>>>(x);
    attn_kernel<<<256, 256, attn_smem>>>();
    proj_kernel<<<dim3(8, 64), 256>>>(out, bp);
}

// round 13
// speedup vs baseline: 1.2616x; 1.1489x over previous
#include <cuda_runtime.h>
#include <cuda_fp16.h>
#include <math.h>

// Problem constants
#define BB 8
#define TT 2048
#define CC 1024
#define DD 64
#define MM (BB*TT)          // 16384 rows

// ---------------------------------------------------------------------------
// Global scratch, all fp16 fragment layouts (allocation-free __device__)
// A-frag (m16k16, 128 u32/tile); B-frag (k16n8, 64 u32/tile)
// ---------------------------------------------------------------------------
__device__ unsigned g_qf [MM*DD/2];   // q,  A-frag per 64-token block (scale*log2e folded)
__device__ unsigned g_kf [MM*DD/2];   // k,  B-frag: [tb][(keyTile8)(dTile4)][64]   (k=d,n=key)
__device__ unsigned g_vf [MM*DD/2];   // v,  B-frag: [tb][(dTile8)(keyTile4)][64]   (k=key,n=d)
__device__ unsigned g_hof[MM*DD/2];   // head_out, A-frag per 64-token block
__device__ unsigned g_wpef[DD*CC/2];      // Wp_eff: [nt(128)][kt(4)][64]
__device__ unsigned g_wqkvf[3*CC*DD/2];   // W q|k|v: [ktG(64)][mat*8+nt(24)][64]

// ---------------------------------------------------------------------------
// helpers
// ---------------------------------------------------------------------------
__device__ __forceinline__ unsigned f2h2(float a, float b) {
    __half2 h = __float22half2_rn(make_float2(a, b));
    return *reinterpret_cast<unsigned*>(&h);
}
__device__ __forceinline__ float ex2(float x) {
    float y; asm("ex2.approx.f32 %0, %1;" : "=f"(y) : "f"(x)); return y;
}
__device__ __forceinline__ void mma16(float* d, const unsigned* a, unsigned b0, unsigned b1) {
    asm volatile("mma.sync.aligned.m16n8k16.row.col.f32.f16.f16.f32 "
                 "{%0,%1,%2,%3},{%4,%5,%6,%7},{%8,%9},{%0,%1,%2,%3};"
                 : "+f"(d[0]), "+f"(d[1]), "+f"(d[2]), "+f"(d[3])
                 : "r"(a[0]), "r"(a[1]), "r"(a[2]), "r"(a[3]), "r"(b0), "r"(b1));
}
__device__ __forceinline__ int aswz(int L) { return L ^ (L >> 3); }
// A-frag u32 address within a 64row x 64k block (4x4 tiles of 132 u, swizzled)
__device__ __forceinline__ int a_addr(int row, int k) {    // k even
    return ((row >> 4)*4 + (k >> 4)) * 132
         + aswz(((row & 7) << 2) | ((k >> 1) & 3)) * 4
         + ((row >> 3) & 1) + (((k >> 3) & 1) << 1);
}
__device__ __forceinline__ int bf_idx(int k, int n) {      // k even
    return ((((n & 7) << 2) | ((k >> 1) & 3)) << 1) + ((k >> 3) & 1);
}

// ---------------------------------------------------------------------------
// Kernel 1 (prep): Wp_eff fold + weights -> fp16 B-frag layouts (R10 version).
// ---------------------------------------------------------------------------
__global__ __launch_bounds__(256) void prep_kernel(const float* __restrict__ Wq,
                                                   const float* __restrict__ Wk,
                                                   const float* __restrict__ Wv,
                                                   const float* __restrict__ Wp) {
    int idx2 = blockIdx.x * 256 + threadIdx.x;     // 0..65535
    int pid = idx2 >> 1, hh = idx2 & 1;
    {
        int d0 = (pid >> 10) * 2, j = pid & 1023;
        float s0 = 0.f, s1 = 0.f;
#pragma unroll
        for (int h = hh*8; h < hh*8 + 8; h++) {
            s0 += Wp[(h*64 + d0    )*1024 + j];
            s1 += Wp[(h*64 + d0 + 1)*1024 + j];
        }
        s0 += __shfl_xor_sync(0xffffffffu, s0, 1);
        s1 += __shfl_xor_sync(0xffffffffu, s1, 1);
        if (!hh)
            g_wpef[(j >> 3)*256 + (d0 >> 4)*64 + bf_idx(d0, j)] = f2h2(s0, s1);
    }
    {
        const float qs = 0.03125f * 1.44269504088896f;
        int c0 = (pid >> 6) * 2, n = pid & 63;
        int ba = (c0 >> 4)*1536 + (n >> 3)*64 + bf_idx(c0, n);
        if (!hh) {
            g_wqkvf[ba]        = f2h2(Wq[c0*64 + n]*qs, Wq[(c0+1)*64 + n]*qs);
            g_wqkvf[ba + 512]  = f2h2(Wk[c0*64 + n],    Wk[(c0+1)*64 + n]);
        } else {
            g_wqkvf[ba + 1024] = f2h2(Wv[c0*64 + n],    Wv[(c0+1)*64 + n]);
        }
    }
}

// ---------------------------------------------------------------------------
// Kernel 2: fused QKV (EXACT R10 version, 78.3us baseline).
// ---------------------------------------------------------------------------
__global__ __launch_bounds__(256, 2) void qkv_kernel(const float* __restrict__ x) {
    extern __shared__ unsigned smu[];
    const int t = threadIdx.x, lane = t & 31, w = t >> 5;
    const int rowBase = blockIdx.x * 64;
    const int m0t = (w & 1) * 2;
    const int ntb = (w >> 1) * 6;

    float acc[2][6][4];
#pragma unroll
    for (int mi = 0; mi < 2; mi++)
#pragma unroll
        for (int ni = 0; ni < 6; ni++)
#pragma unroll
            for (int r = 0; r < 4; r++) acc[mi][ni][r] = 0.f;

    const int arow = t >> 2, acol4 = (t & 3) * 4;
    float4 xr[4];
#pragma unroll
    for (int q = 0; q < 4; q++)
        xr[q] = *(const float4*)&x[(size_t)(rowBase + arow)*CC + q*16 + acol4];
#pragma unroll
    for (int q = 0; q < 4; q++) {
        int k = q*16 + acol4;
        smu[a_addr(arow, k)]     = f2h2(xr[q].x, xr[q].y);
        smu[a_addr(arow, k + 2)] = f2h2(xr[q].z, xr[q].w);
    }
    __syncthreads();

    for (int k0 = 0; k0 < CC; k0 += 64) {
        const unsigned* As = smu + ((k0 >> 6) & 1) * 2112;
        const int ktG = k0 >> 4;
        const bool more = (k0 + 64) < CC;
        if (more) {
#pragma unroll
            for (int q = 0; q < 4; q++)
                xr[q] = *(const float4*)&x[(size_t)(rowBase + arow)*CC + k0 + 64 + q*16 + acol4];
        }
#pragma unroll
        for (int ks = 0; ks < 4; ks++) {
            uint4 v0 = *(const uint4*)&As[(m0t*4 + ks)*132 + aswz(lane)*4];
            uint4 v1 = *(const uint4*)&As[((m0t+1)*4 + ks)*132 + aswz(lane)*4];
            unsigned a0[4] = {v0.x, v0.y, v0.z, v0.w};
            unsigned a1[4] = {v1.x, v1.y, v1.z, v1.w};
#pragma unroll
            for (int ni = 0; ni < 6; ni++) {
                uint2 b = *(const uint2*)&g_wqkvf[(ktG + ks)*1536 + (ntb + ni)*64 + 2*lane];
                mma16(acc[0][ni], a0, b.x, b.y);
                mma16(acc[1][ni], a1, b.x, b.y);
            }
        }
        if (more) {
            unsigned* An = smu + (((k0 >> 6) & 1) ^ 1) * 2112;
#pragma unroll
            for (int q = 0; q < 4; q++) {
                int k = q*16 + acol4;
                An[a_addr(arow, k)]     = f2h2(xr[q].x, xr[q].y);
                An[a_addr(arow, k + 2)] = f2h2(xr[q].z, xr[q].w);
            }
        }
        __syncthreads();
    }

    // ---- epilogue: stage C-frags into fp16 operand layouts ----
    __half* vstage = (__half*)(smu + 6272);
#pragma unroll
    for (int mi = 0; mi < 2; mi++) {
#pragma unroll
        for (int ni = 0; ni < 6; ni++) {
            int row0 = (w & 1)*32 + mi*16 + (lane >> 2);
            int col0 = (ntb + ni)*8 + 2*(lane & 3);
            int mat = col0 >> 6;
            if (mat == 0) {
                smu[a_addr(row0,     col0)] = f2h2(acc[mi][ni][0], acc[mi][ni][1]);
                smu[a_addr(row0 + 8, col0)] = f2h2(acc[mi][ni][2], acc[mi][ni][3]);
            } else if (mat == 1) {
                int d = col0 - 64;
                int t0 = ((row0 >> 3)*4 + (d >> 4))*64;
                smu[4224 + t0       + bf_idx(d, row0)] = f2h2(acc[mi][ni][0], acc[mi][ni][1]);
                smu[4224 + t0 + 256 + bf_idx(d, row0)] = f2h2(acc[mi][ni][2], acc[mi][ni][3]);
            } else {
                int d = col0 - 128;
                int u0 = (d >> 3)*256 + (row0 >> 4)*64;
                vstage[(u0 + bf_idx(row0 & 63, d))*2     + (row0 & 1)] = __float2half_rn(acc[mi][ni][0]);
                vstage[(u0 + bf_idx(row0 & 63, d+1))*2   + (row0 & 1)] = __float2half_rn(acc[mi][ni][1]);
                int r8 = row0 + 8;
                int u8 = (d >> 3)*256 + (r8 >> 4)*64;
                vstage[(u8 + bf_idx(r8 & 63, d))*2   + (r8 & 1)] = __float2half_rn(acc[mi][ni][2]);
                vstage[(u8 + bf_idx(r8 & 63, d+1))*2 + (r8 & 1)] = __float2half_rn(acc[mi][ni][3]);
            }
        }
    }
    __syncthreads();

    const size_t rb = blockIdx.x;
#pragma unroll
    for (int j = 0; j < 2; j++) {
        int tile = w*2 + j;
        uint4 v = *(const uint4*)&smu[tile*132 + aswz(lane)*4];
        *(uint4*)&g_qf[rb*2048 + tile*128 + lane*4] = v;
    }
#pragma unroll
    for (int j = 0; j < 2; j++) {
        int u = t + 256*j;
        *(uint4*)&g_kf[rb*2048 + 4*u] = *(const uint4*)&smu[4224 + 4*u];
    }
#pragma unroll
    for (int j = 0; j < 2; j++) {
        int u = t + 256*j;
        *(uint4*)&g_vf[rb*2048 + 4*u] = *(const uint4*)&smu[6272 + 4*u];
    }
}

// ---------------------------------------------------------------------------
// Kernel 3: causal flash attention, warp = 32 rows x 16 keys (mh = w&1,
// kq = w>>2? no: kq = w>>1). Each K/V B-frag LDS is shared by 2 m-tiles ->
// 16 b-loads/warp/tile (was 32). O is a 4-way key-quarter fp32 partial,
// merged once per block via padded smem scratch (pure adds; no-max softmax).
// Unpaired LPT grid: 256 blocks, qt descending. 1 sync per KV tile.
// smem (u32): K bufs 0/2048, V bufs 4096/6144 (loop);
//             scr 0..16896 (4 x 64 x 66 fp32, epilogue, overlaps K/V);
//             Ps @16896 (2112); lsh(f32 x 256) @19008. total 19264 u32.
// ---------------------------------------------------------------------------
__global__ __launch_bounds__(256, 1) void attn_kernel() {
    extern __shared__ unsigned smu[];
    unsigned* Ps = smu + 16896;
    float* lsh = (float*)(smu + 19008);   // [64 rows][4 quarters]
    float* scr = (float*)smu;             // [kq][row][66]

    const int t = threadIdx.x, lane = t & 31, w = t >> 5;
    const int bid = blockIdx.x;
    const int batch = bid & 7;
    const int qt = 31 - (bid >> 3);       // big q-tiles first
    const int mh = w & 1;                 // row half (32 rows)
    const int kq = w >> 1;                // key quarter (16 keys)
    const int rl = lane >> 2;

    const size_t qrb = batch*32 + qt;
    const int ntiles = qt + 1;

    // Q fragments for BOTH m-tiles of this warp's row half
    unsigned qf[2][4][4];
#pragma unroll
    for (int mt = 0; mt < 2; mt++)
#pragma unroll
        for (int kt = 0; kt < 4; kt++) {
            uint4 v = *(const uint4*)&g_qf[qrb*2048 + ((mh*2 + mt)*4 + kt)*128 + lane*4];
            qf[mt][kt][0] = v.x; qf[mt][kt][1] = v.y; qf[mt][kt][2] = v.z; qf[mt][kt][3] = v.w;
        }
    // prefetch + store KV tile 0
    uint4 kr[2], vr[2];
    {
        size_t tb = batch*32;
#pragma unroll
        for (int j = 0; j < 2; j++) {
            kr[j] = *(const uint4*)&g_kf[tb*2048 + 4*(t + 256*j)];
            vr[j] = *(const uint4*)&g_vf[tb*2048 + 4*(t + 256*j)];
        }
    }
#pragma unroll
    for (int j = 0; j < 2; j++) {
        *(uint4*)&smu[4*(t + 256*j)]        = kr[j];
        *(uint4*)&smu[4096 + 4*(t + 256*j)] = vr[j];
    }

    float lAr[2] = {0.f, 0.f}, lBr[2] = {0.f, 0.f};
    float oacc[2][8][4];
#pragma unroll
    for (int mt = 0; mt < 2; mt++)
#pragma unroll
        for (int ni = 0; ni < 8; ni++)
#pragma unroll
            for (int r = 0; r < 4; r++) oacc[mt][ni][r] = 0.f;
    __syncthreads();

    for (int it = 0; it < ntiles; it++) {
        const unsigned* Kb = smu + (it & 1)*2048;
        const unsigned* Vb = smu + 4096 + (it & 1)*2048;

        // S' = Q @ K^T over this warp's 16 keys, 32 rows (b shared by 2 mt)
        float sacc[2][2][4];
#pragma unroll
        for (int mt = 0; mt < 2; mt++)
#pragma unroll
            for (int ntl = 0; ntl < 2; ntl++)
#pragma unroll
                for (int r = 0; r < 4; r++) sacc[mt][ntl][r] = 0.f;
#pragma unroll
        for (int ks = 0; ks < 4; ks++)
#pragma unroll
            for (int ntl = 0; ntl < 2; ntl++) {
                int nt = kq*2 + ntl;
                uint2 b = *(const uint2*)&Kb[(nt*4 + ks)*64 + 2*lane];
                mma16(sacc[0][ntl], qf[0][ks], b.x, b.y);
                mma16(sacc[1][ntl], qf[1][ks], b.x, b.y);
            }

        // prefetch next KV tile
        const bool more = (it + 1) < ntiles;
        if (more) {
            size_t tb = batch*32 + it + 1;
#pragma unroll
            for (int j = 0; j < 2; j++) {
                kr[j] = *(const uint4*)&g_kf[tb*2048 + 4*(t + 256*j)];
                vr[j] = *(const uint4*)&g_vf[tb*2048 + 4*(t + 256*j)];
            }
        }

        // causal mask on diagonal tile
        if (it == ntiles - 1) {
#pragma unroll
            for (int mt = 0; mt < 2; mt++) {
                int rA = mh*32 + mt*16 + rl;
#pragma unroll
                for (int ntl = 0; ntl < 2; ntl++) {
                    int c0 = kq*16 + ntl*8 + 2*(lane & 3);
                    if (c0     > rA)     sacc[mt][ntl][0] = -1e30f;
                    if (c0 + 1 > rA)     sacc[mt][ntl][1] = -1e30f;
                    if (c0     > rA + 8) sacc[mt][ntl][2] = -1e30f;
                    if (c0 + 1 > rA + 8) sacc[mt][ntl][3] = -1e30f;
                }
            }
        }

        // P = 2^S' into A-fragment registers (C-frag == A-frag map)
        unsigned pa[2][4];
#pragma unroll
        for (int mt = 0; mt < 2; mt++)
#pragma unroll
            for (int ntl = 0; ntl < 2; ntl++) {
                float p0 = ex2(sacc[mt][ntl][0]);
                float p1 = ex2(sacc[mt][ntl][1]);
                float p2 = ex2(sacc[mt][ntl][2]);
                float p3 = ex2(sacc[mt][ntl][3]);
                lAr[mt] += p0 + p1;
                lBr[mt] += p2 + p3;
                pa[mt][ntl*2]     = f2h2(p0, p1);
                pa[mt][ntl*2 + 1] = f2h2(p2, p3);
            }

        // O += P @ V over this warp's 16 keys, all 64 d (b shared by 2 mt)
#pragma unroll
        for (int ni = 0; ni < 8; ni++) {
            uint2 b = *(const uint2*)&Vb[(ni*4 + kq)*64 + 2*lane];
            mma16(oacc[0][ni], pa[0], b.x, b.y);
            mma16(oacc[1][ni], pa[1], b.x, b.y);
        }

        // store next KV tile into other buffer
        if (more) {
            unsigned nb = ((it + 1) & 1) * 2048;
#pragma unroll
            for (int j = 0; j < 2; j++) {
                *(uint4*)&smu[nb + 4*(t + 256*j)]        = kr[j];
                *(uint4*)&smu[4096 + nb + 4*(t + 256*j)] = vr[j];
            }
        }
        __syncthreads();
    }

    // ---- epilogue: reduce l across lanes, dump O partials, 4-way merge ----
#pragma unroll
    for (int mt = 0; mt < 2; mt++) {
        lAr[mt] += __shfl_xor_sync(0xffffffffu, lAr[mt], 1);
        lAr[mt] += __shfl_xor_sync(0xffffffffu, lAr[mt], 2);
        lBr[mt] += __shfl_xor_sync(0xffffffffu, lBr[mt], 1);
        lBr[mt] += __shfl_xor_sync(0xffffffffu, lBr[mt], 2);
        if ((lane & 3) == 0) {
            int rA = mh*32 + mt*16 + rl;
            lsh[rA*4 + kq]       = lAr[mt];
            lsh[(rA + 8)*4 + kq] = lBr[mt];
        }
        // O partial -> scratch (row stride 66 avoids bank conflicts)
#pragma unroll
        for (int ni = 0; ni < 8; ni++) {
            int rA = mh*32 + mt*16 + rl;
            int col = ni*8 + 2*(lane & 3);
            *(float2*)&scr[kq*4224 + rA*66 + col] =
                make_float2(oacc[mt][ni][0], oacc[mt][ni][1]);
            *(float2*)&scr[kq*4224 + (rA + 8)*66 + col] =
                make_float2(oacc[mt][ni][2], oacc[mt][ni][3]);
        }
    }
    __syncthreads();

    // merge roles: warp w -> rows (w>>1)*16..+15, d-half (w&1)*32
    {
        const int mt4 = w >> 1, dh = w & 1;
        const int r4A = mt4*16 + rl, r4B = r4A + 8;
        float iA = 1.0f / (lsh[r4A*4] + lsh[r4A*4+1] + lsh[r4A*4+2] + lsh[r4A*4+3]);
        float iB = 1.0f / (lsh[r4B*4] + lsh[r4B*4+1] + lsh[r4B*4+2] + lsh[r4B*4+3]);
#pragma unroll
        for (int ni = 0; ni < 4; ni++) {
            int c = dh*32 + ni*8 + 2*(lane & 3);
            float v0 = 0.f, v1 = 0.f, v2 = 0.f, v3 = 0.f;
#pragma unroll
            for (int q = 0; q < 4; q++) {
                float2 pA = *(const float2*)&scr[q*4224 + r4A*66 + c];
                float2 pB = *(const float2*)&scr[q*4224 + r4B*66 + c];
                v0 += pA.x; v1 += pA.y; v2 += pB.x; v3 += pB.y;
            }
            Ps[a_addr(r4A, c)] = f2h2(v0*iA, v1*iA);
            Ps[a_addr(r4B, c)] = f2h2(v2*iB, v3*iB);
        }
    }
    __syncthreads();
#pragma unroll
    for (int j = 0; j < 2; j++) {
        int tile = w*2 + j;
        uint4 v = *(const uint4*)&Ps[tile*132 + aswz(lane)*4];
        *(uint4*)&g_hof[qrb*2048 + tile*128 + lane*4] = v;
    }
}

// ---------------------------------------------------------------------------
// Kernel 4: out = ho @ Wp_eff + bp (EXACT R10 version, 78.3us baseline).
// ---------------------------------------------------------------------------
__global__ __launch_bounds__(256) void proj_kernel(float* __restrict__ out,
                                                   const float* __restrict__ bp) {
    __shared__ unsigned Bs[4096];       // [ntLocal(16)][kt(4)][64]

    const int t = threadIdx.x, lane = t & 31, w = t >> 5;
    const int ntBase = blockIdx.x * 16;
    const int colBase = blockIdx.x * 128;
    const int mt = w & 3;
    const int ntb = (w >> 2) * 8;

#pragma unroll
    for (int j = 0; j < 4; j++) {
        int u = t + 256*j;
        *(uint4*)&Bs[4*u] = *(const uint4*)&g_wpef[(size_t)ntBase*256 + 4*u];
    }
    float2 bias[8];
#pragma unroll
    for (int ni = 0; ni < 8; ni++)
        bias[ni] = *(const float2*)&bp[colBase + (ntb + ni)*8 + 2*(lane & 3)];
    __syncthreads();

    const size_t rb0 = (size_t)blockIdx.y * 4;
    uint4 a0[4];
#pragma unroll
    for (int ks = 0; ks < 4; ks++)
        a0[ks] = *(const uint4*)&g_hof[rb0*2048 + (mt*4 + ks)*128 + lane*4];

    for (int i = 0; i < 4; i++) {
        const size_t rb = rb0 + i;
        uint4 an[4];
        if (i < 3) {
#pragma unroll
            for (int ks = 0; ks < 4; ks++)
                an[ks] = *(const uint4*)&g_hof[(rb + 1)*2048 + (mt*4 + ks)*128 + lane*4];
        }

        float acc[8][4];
#pragma unroll
        for (int ni = 0; ni < 8; ni++)
#pragma unroll
            for (int r = 0; r < 4; r++) acc[ni][r] = 0.f;

#pragma unroll
        for (int ks = 0; ks < 4; ks++) {
            unsigned a[4] = {a0[ks].x, a0[ks].y, a0[ks].z, a0[ks].w};
#pragma unroll
            for (int ni = 0; ni < 8; ni++) {
                uint2 b = *(const uint2*)&Bs[((ntb + ni)*4 + ks)*64 + 2*lane];
                mma16(acc[ni], a, b.x, b.y);
            }
        }

        int row = (int)rb*64 + mt*16 + (lane >> 2);
#pragma unroll
        for (int ni = 0; ni < 8; ni++) {
            int col = colBase + (ntb + ni)*8 + 2*(lane & 3);
            *(float2*)&out[(size_t)row*CC + col] =
                make_float2(acc[ni][0] + bias[ni].x, acc[ni][1] + bias[ni].y);
            *(float2*)&out[(size_t)(row + 8)*CC + col] =
                make_float2(acc[ni][2] + bias[ni].x, acc[ni][3] + bias[ni].y);
        }
#pragma unroll
        for (int ks = 0; ks < 4; ks++) a0[ks] = an[ks];
    }
}

// ---------------------------------------------------------------------------
// Launch
// ---------------------------------------------------------------------------
extern "C" void kernel_launch(void* const* d_in, const int* in_sizes, int n_in,
                              void* d_out, int out_size) {
    const float* x  = (const float*)d_in[0];
    const float* Wq = (const float*)d_in[1];
    const float* Wk = (const float*)d_in[2];
    const float* Wv = (const float*)d_in[3];
    const float* Wp = (const float*)d_in[4];
    const float* bp = (const float*)d_in[5];
    float* out = (float*)d_out;

    const int qkv_smem  = 8320 * 4;    // 33280 B
    const int attn_smem = 19264 * 4;   // 77056 B

    cudaFuncSetAttribute(qkv_kernel,  cudaFuncAttributeMaxDynamicSharedMemorySize, qkv_smem);
    cudaFuncSetAttribute(attn_kernel, cudaFuncAttributeMaxDynamicSharedMemorySize, attn_smem);

    prep_kernel<<<256, 256>>>(Wq, Wk, Wv, Wp);
    qkv_kernel<<<MM/64, 256, qkv_smem>>>(x);
    attn_kernel<<<256, 256, attn_smem>>>();
    proj_kernel<<<dim3(8, 64), 256>>>(out, bp);
}

// round 14
// speedup vs baseline: 1.4030x; 1.1121x over previous
#include <cuda_runtime.h>
#include <cuda_fp16.h>
#include <math.h>

// Problem constants
#define BB 8
#define TT 2048
#define CC 1024
#define DD 64
#define MM (BB*TT)          // 16384 rows

// ---------------------------------------------------------------------------
// Global scratch, all fp16 fragment layouts (allocation-free __device__)
// A-frag (m16k16, 128 u32/tile); B-frag (k16n8, 64 u32/tile)
// ---------------------------------------------------------------------------
__device__ unsigned g_qf [MM*DD/2];   // q,  A-frag per 64-token block (scale*log2e folded)
__device__ unsigned g_kf [MM*DD/2];   // k,  B-frag: [tb][(keyTile8)(dTile4)][64]   (k=d,n=key)
__device__ unsigned g_vf [MM*DD/2];   // v,  B-frag: [tb][(dTile8)(keyTile4)][64]   (k=key,n=d)
__device__ unsigned g_wpef[DD*CC/2];      // Wp_eff: [nt(128)][kt(4)][64]
__device__ unsigned g_wqkvf[3*CC*DD/2];   // W q|k|v: [ktG(64)][mat*8+nt(24)][64]

// ---------------------------------------------------------------------------
// helpers
// ---------------------------------------------------------------------------
__device__ __forceinline__ unsigned f2h2(float a, float b) {
    __half2 h = __float22half2_rn(make_float2(a, b));
    return *reinterpret_cast<unsigned*>(&h);
}
__device__ __forceinline__ float ex2(float x) {
    float y; asm("ex2.approx.f32 %0, %1;" : "=f"(y) : "f"(x)); return y;
}
__device__ __forceinline__ void mma16(float* d, const unsigned* a, unsigned b0, unsigned b1) {
    asm volatile("mma.sync.aligned.m16n8k16.row.col.f32.f16.f16.f32 "
                 "{%0,%1,%2,%3},{%4,%5,%6,%7},{%8,%9},{%0,%1,%2,%3};"
                 : "+f"(d[0]), "+f"(d[1]), "+f"(d[2]), "+f"(d[3])
                 : "r"(a[0]), "r"(a[1]), "r"(a[2]), "r"(a[3]), "r"(b0), "r"(b1));
}
__device__ __forceinline__ int aswz(int L) { return L ^ (L >> 3); }
// A-frag u32 address within a 64row x 64k block (4x4 tiles of 132 u, swizzled)
__device__ __forceinline__ int a_addr(int row, int k) {    // k even
    return ((row >> 4)*4 + (k >> 4)) * 132
         + aswz(((row & 7) << 2) | ((k >> 1) & 3)) * 4
         + ((row >> 3) & 1) + (((k >> 3) & 1) << 1);
}
__device__ __forceinline__ int bf_idx(int k, int n) {      // k even
    return ((((n & 7) << 2) | ((k >> 1) & 3)) << 1) + ((k >> 3) & 1);
}
__device__ __forceinline__ void bar64(int id) {
    asm volatile("bar.sync %0, %1;" :: "r"(id), "r"(64) : "memory");
}
__device__ __forceinline__ void cpa16(unsigned saddr, const void* g) {
    asm volatile("cp.async.cg.shared.global [%0], [%1], 16;" :: "r"(saddr), "l"(g));
}
#define CP_COMMIT() asm volatile("cp.async.commit_group;" ::: "memory")
#define CP_WAIT0()  asm volatile("cp.async.wait_group 0;" ::: "memory")

// ---------------------------------------------------------------------------
// Kernel 1 (prep): Wp_eff fold + weights -> fp16 B-frag layouts (R10 version).
// ---------------------------------------------------------------------------
__global__ __launch_bounds__(256) void prep_kernel(const float* __restrict__ Wq,
                                                   const float* __restrict__ Wk,
                                                   const float* __restrict__ Wv,
                                                   const float* __restrict__ Wp) {
    int idx2 = blockIdx.x * 256 + threadIdx.x;     // 0..65535
    int pid = idx2 >> 1, hh = idx2 & 1;
    {
        int d0 = (pid >> 10) * 2, j = pid & 1023;
        float s0 = 0.f, s1 = 0.f;
#pragma unroll
        for (int h = hh*8; h < hh*8 + 8; h++) {
            s0 += Wp[(h*64 + d0    )*1024 + j];
            s1 += Wp[(h*64 + d0 + 1)*1024 + j];
        }
        s0 += __shfl_xor_sync(0xffffffffu, s0, 1);
        s1 += __shfl_xor_sync(0xffffffffu, s1, 1);
        if (!hh)
            g_wpef[(j >> 3)*256 + (d0 >> 4)*64 + bf_idx(d0, j)] = f2h2(s0, s1);
    }
    {
        const float qs = 0.03125f * 1.44269504088896f;
        int c0 = (pid >> 6) * 2, n = pid & 63;
        int ba = (c0 >> 4)*1536 + (n >> 3)*64 + bf_idx(c0, n);
        if (!hh) {
            g_wqkvf[ba]        = f2h2(Wq[c0*64 + n]*qs, Wq[(c0+1)*64 + n]*qs);
            g_wqkvf[ba + 512]  = f2h2(Wk[c0*64 + n],    Wk[(c0+1)*64 + n]);
        } else {
            g_wqkvf[ba + 1024] = f2h2(Wv[c0*64 + n],    Wv[(c0+1)*64 + n]);
        }
    }
}

// ---------------------------------------------------------------------------
// Kernel 2: fused QKV (EXACT R10 version, 78.3us baseline).
// ---------------------------------------------------------------------------
__global__ __launch_bounds__(256, 2) void qkv_kernel(const float* __restrict__ x) {
    extern __shared__ unsigned smu[];
    const int t = threadIdx.x, lane = t & 31, w = t >> 5;
    const int rowBase = blockIdx.x * 64;
    const int m0t = (w & 1) * 2;
    const int ntb = (w >> 1) * 6;

    float acc[2][6][4];
#pragma unroll
    for (int mi = 0; mi < 2; mi++)
#pragma unroll
        for (int ni = 0; ni < 6; ni++)
#pragma unroll
            for (int r = 0; r < 4; r++) acc[mi][ni][r] = 0.f;

    const int arow = t >> 2, acol4 = (t & 3) * 4;
    float4 xr[4];
#pragma unroll
    for (int q = 0; q < 4; q++)
        xr[q] = *(const float4*)&x[(size_t)(rowBase + arow)*CC + q*16 + acol4];
#pragma unroll
    for (int q = 0; q < 4; q++) {
        int k = q*16 + acol4;
        smu[a_addr(arow, k)]     = f2h2(xr[q].x, xr[q].y);
        smu[a_addr(arow, k + 2)] = f2h2(xr[q].z, xr[q].w);
    }
    __syncthreads();

    for (int k0 = 0; k0 < CC; k0 += 64) {
        const unsigned* As = smu + ((k0 >> 6) & 1) * 2112;
        const int ktG = k0 >> 4;
        const bool more = (k0 + 64) < CC;
        if (more) {
#pragma unroll
            for (int q = 0; q < 4; q++)
                xr[q] = *(const float4*)&x[(size_t)(rowBase + arow)*CC + k0 + 64 + q*16 + acol4];
        }
#pragma unroll
        for (int ks = 0; ks < 4; ks++) {
            uint4 v0 = *(const uint4*)&As[(m0t*4 + ks)*132 + aswz(lane)*4];
            uint4 v1 = *(const uint4*)&As[((m0t+1)*4 + ks)*132 + aswz(lane)*4];
            unsigned a0[4] = {v0.x, v0.y, v0.z, v0.w};
            unsigned a1[4] = {v1.x, v1.y, v1.z, v1.w};
#pragma unroll
            for (int ni = 0; ni < 6; ni++) {
                uint2 b = *(const uint2*)&g_wqkvf[(ktG + ks)*1536 + (ntb + ni)*64 + 2*lane];
                mma16(acc[0][ni], a0, b.x, b.y);
                mma16(acc[1][ni], a1, b.x, b.y);
            }
        }
        if (more) {
            unsigned* An = smu + (((k0 >> 6) & 1) ^ 1) * 2112;
#pragma unroll
            for (int q = 0; q < 4; q++) {
                int k = q*16 + acol4;
                An[a_addr(arow, k)]     = f2h2(xr[q].x, xr[q].y);
                An[a_addr(arow, k + 2)] = f2h2(xr[q].z, xr[q].w);
            }
        }
        __syncthreads();
    }

    // ---- epilogue: stage C-frags into fp16 operand layouts ----
    __half* vstage = (__half*)(smu + 6272);
#pragma unroll
    for (int mi = 0; mi < 2; mi++) {
#pragma unroll
        for (int ni = 0; ni < 6; ni++) {
            int row0 = (w & 1)*32 + mi*16 + (lane >> 2);
            int col0 = (ntb + ni)*8 + 2*(lane & 3);
            int mat = col0 >> 6;
            if (mat == 0) {
                smu[a_addr(row0,     col0)] = f2h2(acc[mi][ni][0], acc[mi][ni][1]);
                smu[a_addr(row0 + 8, col0)] = f2h2(acc[mi][ni][2], acc[mi][ni][3]);
            } else if (mat == 1) {
                int d = col0 - 64;
                int t0 = ((row0 >> 3)*4 + (d >> 4))*64;
                smu[4224 + t0       + bf_idx(d, row0)] = f2h2(acc[mi][ni][0], acc[mi][ni][1]);
                smu[4224 + t0 + 256 + bf_idx(d, row0)] = f2h2(acc[mi][ni][2], acc[mi][ni][3]);
            } else {
                int d = col0 - 128;
                int u0 = (d >> 3)*256 + (row0 >> 4)*64;
                vstage[(u0 + bf_idx(row0 & 63, d))*2     + (row0 & 1)] = __float2half_rn(acc[mi][ni][0]);
                vstage[(u0 + bf_idx(row0 & 63, d+1))*2   + (row0 & 1)] = __float2half_rn(acc[mi][ni][1]);
                int r8 = row0 + 8;
                int u8 = (d >> 3)*256 + (r8 >> 4)*64;
                vstage[(u8 + bf_idx(r8 & 63, d))*2   + (r8 & 1)] = __float2half_rn(acc[mi][ni][2]);
                vstage[(u8 + bf_idx(r8 & 63, d+1))*2 + (r8 & 1)] = __float2half_rn(acc[mi][ni][3]);
            }
        }
    }
    __syncthreads();

    const size_t rb = blockIdx.x;
#pragma unroll
    for (int j = 0; j < 2; j++) {
        int tile = w*2 + j;
        uint4 v = *(const uint4*)&smu[tile*132 + aswz(lane)*4];
        *(uint4*)&g_qf[rb*2048 + tile*128 + lane*4] = v;
    }
#pragma unroll
    for (int j = 0; j < 2; j++) {
        int u = t + 256*j;
        *(uint4*)&g_kf[rb*2048 + 4*u] = *(const uint4*)&smu[4224 + 4*u];
    }
#pragma unroll
    for (int j = 0; j < 2; j++) {
        int u = t + 256*j;
        *(uint4*)&g_vf[rb*2048 + 4*u] = *(const uint4*)&smu[6272 + 4*u];
    }
}

// ---------------------------------------------------------------------------
// Kernel 3: causal flash attention + FUSED PROJECTION with smem-resident
// Wp_eff. Mainloop EXACTLY R10 (no-max softmax, register P, 1 sync/tile,
// unpaired LPT grid 256 blocks). Wp_eff (128 KB) streamed into smem via
// fire-and-forget cp.async at start, waited only before the epilogue.
// Epilogue: merge -> ho fp16 frags in Ps -> per-warp 128-col projection
// (B from smem LDS, bias from smem) -> direct out stores. No g_hof.
// smem (u32): K 0/2048, V 4096/6144, Ps @8192 (2112), lsh @10304 (128),
//             Wps @10432 (32768), bias @43200 (1024). total 44224 u32.
// ---------------------------------------------------------------------------
__global__ __launch_bounds__(256, 1) void attn_kernel(float* __restrict__ out,
                                                      const float* __restrict__ bp) {
    extern __shared__ unsigned smu[];
    unsigned* Ps = smu + 8192;
    float* lsh = (float*)(smu + 10304);
    unsigned* Wps = smu + 10432;
    float* bias_sh = (float*)(smu + 43200);
    float* scr = (float*)smu;

    const int t = threadIdx.x, lane = t & 31, w = t >> 5;
    const int bid = blockIdx.x;
    const int batch = bid & 7;
    const int qt = 31 - (bid >> 3);       // big q-tiles first (LPT)
    const int half_id = w & 1;
    const int mt = w >> 1;
    const int rl = lane >> 2;
    const int rA = mt*16 + rl, rB = rA + 8;
    const int colb = half_id * 32;
    const int barid = 1 + mt;

    const size_t qrb = batch*32 + qt;
    const int ntiles = qt + 1;

    // fire-and-forget: Wp_eff gmem -> smem (32 x 16B per thread), waited later
    {
        const unsigned sbase = (unsigned)__cvta_generic_to_shared(Wps);
#pragma unroll
        for (int j = 0; j < 32; j++) {
            int u = t + 256*j;            // uint4 index, 0..8191
            cpa16(sbase + u*16, &g_wpef[4*u]);
        }
        CP_COMMIT();
    }
    // bias -> smem
    *(float4*)&bias_sh[t*4] = *(const float4*)&bp[t*4];

    // Q fragments: gmem -> registers (4 k16 tiles)
    unsigned qf[4][4];
#pragma unroll
    for (int kt = 0; kt < 4; kt++) {
        uint4 v = *(const uint4*)&g_qf[qrb*2048 + (mt*4 + kt)*128 + lane*4];
        qf[kt][0] = v.x; qf[kt][1] = v.y; qf[kt][2] = v.z; qf[kt][3] = v.w;
    }
    // prefetch + store KV tile 0
    uint4 kr[2], vr[2];
    {
        size_t tb = batch*32;
#pragma unroll
        for (int j = 0; j < 2; j++) {
            kr[j] = *(const uint4*)&g_kf[tb*2048 + 4*(t + 256*j)];
            vr[j] = *(const uint4*)&g_vf[tb*2048 + 4*(t + 256*j)];
        }
    }
#pragma unroll
    for (int j = 0; j < 2; j++) {
        *(uint4*)&smu[4*(t + 256*j)]        = kr[j];
        *(uint4*)&smu[4096 + 4*(t + 256*j)] = vr[j];
    }

    float lAr = 0.f, lBr = 0.f;
    float oacc[8][4];
#pragma unroll
    for (int ni = 0; ni < 8; ni++)
#pragma unroll
        for (int r = 0; r < 4; r++) oacc[ni][r] = 0.f;
    __syncthreads();

    for (int it = 0; it < ntiles; it++) {
        const unsigned* Kb = smu + (it & 1)*2048;
        const unsigned* Vb = smu + 4096 + (it & 1)*2048;

        float sacc[4][4];
#pragma unroll
        for (int ni = 0; ni < 4; ni++)
#pragma unroll
            for (int r = 0; r < 4; r++) sacc[ni][r] = 0.f;
#pragma unroll
        for (int ks = 0; ks < 4; ks++)
#pragma unroll
            for (int ni = 0; ni < 4; ni++) {
                uint2 b = *(const uint2*)&Kb[((half_id*4 + ni)*4 + ks)*64 + 2*lane];
                mma16(sacc[ni], qf[ks], b.x, b.y);
            }

        const bool more = (it + 1) < ntiles;
        if (more) {
            size_t tb = batch*32 + it + 1;
#pragma unroll
            for (int j = 0; j < 2; j++) {
                kr[j] = *(const uint4*)&g_kf[tb*2048 + 4*(t + 256*j)];
                vr[j] = *(const uint4*)&g_vf[tb*2048 + 4*(t + 256*j)];
            }
        }

        if (it == ntiles - 1) {
#pragma unroll
            for (int ni = 0; ni < 4; ni++) {
                int c0 = colb + ni*8 + 2*(lane & 3);
                if (c0     > rA) sacc[ni][0] = -1e30f;
                if (c0 + 1 > rA) sacc[ni][1] = -1e30f;
                if (c0     > rB) sacc[ni][2] = -1e30f;
                if (c0 + 1 > rB) sacc[ni][3] = -1e30f;
            }
        }

        unsigned pa[2][4];
#pragma unroll
        for (int ni = 0; ni < 4; ni++) {
            float p0 = ex2(sacc[ni][0]);
            float p1 = ex2(sacc[ni][1]);
            float p2 = ex2(sacc[ni][2]);
            float p3 = ex2(sacc[ni][3]);
            lAr += p0 + p1;
            lBr += p2 + p3;
            pa[ni >> 1][(ni & 1)*2]     = f2h2(p0, p1);
            pa[ni >> 1][(ni & 1)*2 + 1] = f2h2(p2, p3);
        }

#pragma unroll
        for (int p = 0; p < 2; p++)
#pragma unroll
            for (int ni = 0; ni < 8; ni++) {
                uint2 b = *(const uint2*)&Vb[(ni*4 + half_id*2 + p)*64 + 2*lane];
                mma16(oacc[ni], pa[p], b.x, b.y);
            }

        if (more) {
            unsigned nb = ((it + 1) & 1) * 2048;
#pragma unroll
            for (int j = 0; j < 2; j++) {
                *(uint4*)&smu[nb + 4*(t + 256*j)]        = kr[j];
                *(uint4*)&smu[4096 + nb + 4*(t + 256*j)] = vr[j];
            }
        }
        __syncthreads();
    }

    // ---- reduce l across lanes, then merge the two column halves ----
    lAr += __shfl_xor_sync(0xffffffffu, lAr, 1);
    lAr += __shfl_xor_sync(0xffffffffu, lAr, 2);
    lBr += __shfl_xor_sync(0xffffffffu, lBr, 1);
    lBr += __shfl_xor_sync(0xffffffffu, lBr, 2);
    if ((lane & 3) == 0) {
        lsh[rA*2 + half_id] = lAr;
        lsh[rB*2 + half_id] = lBr;
    }
    bar64(barid);
    float iA = 1.0f / (lsh[rA*2] + lsh[rA*2 + 1]);
    float iB = 1.0f / (lsh[rB*2] + lsh[rB*2 + 1]);

    float* sc = scr + mt*1024;
    if (half_id) {
#pragma unroll
        for (int ni = 0; ni < 8; ni++) {
            sc[(ni*4 + 0)*32 + lane] = oacc[ni][0];
            sc[(ni*4 + 1)*32 + lane] = oacc[ni][1];
            sc[(ni*4 + 2)*32 + lane] = oacc[ni][2];
            sc[(ni*4 + 3)*32 + lane] = oacc[ni][3];
        }
    }
    bar64(barid);
    if (!half_id) {
#pragma unroll
        for (int ni = 0; ni < 8; ni++) {
            int d0 = ni*8 + 2*(lane & 3);
            float v0 = (oacc[ni][0] + sc[(ni*4 + 0)*32 + lane]) * iA;
            float v1 = (oacc[ni][1] + sc[(ni*4 + 1)*32 + lane]) * iA;
            float v2 = (oacc[ni][2] + sc[(ni*4 + 2)*32 + lane]) * iB;
            float v3 = (oacc[ni][3] + sc[(ni*4 + 3)*32 + lane]) * iB;
            Ps[a_addr(mt*16 + rl,     d0)] = f2h2(v0, v1);
            Ps[a_addr(mt*16 + rl + 8, d0)] = f2h2(v2, v3);
        }
    }
    CP_WAIT0();          // Wp_eff copies complete (own thread's)
    __syncthreads();     // all threads' copies + Ps visible

    // ---- FUSED PROJECTION: out[64,1024] = ho @ Wp_eff + bp ----
    // Warp w covers cols w*128..+127 (n-tiles w*16..+15). B from smem.
    const int rowG = (int)qrb * 64;
#pragma unroll
    for (int mt2 = 0; mt2 < 4; mt2++) {
        unsigned a[4][4];
#pragma unroll
        for (int kt = 0; kt < 4; kt++) {
            uint4 v = *(const uint4*)&Ps[(mt2*4 + kt)*132 + aswz(lane)*4];
            a[kt][0] = v.x; a[kt][1] = v.y; a[kt][2] = v.z; a[kt][3] = v.w;
        }
        const int row = rowG + mt2*16 + (lane >> 2);
#pragma unroll
        for (int nt = 0; nt < 16; nt++) {
            float acc[4] = {0.f, 0.f, 0.f, 0.f};
#pragma unroll
            for (int kt = 0; kt < 4; kt++) {
                uint2 b = *(const uint2*)&Wps[(w*16 + nt)*256 + kt*64 + 2*lane];
                mma16(acc, a[kt], b.x, b.y);
            }
            const int col = w*128 + nt*8 + 2*(lane & 3);
            float2 bias = *(const float2*)&bias_sh[col];
            *(float2*)&out[(size_t)row*CC + col] =
                make_float2(acc[0] + bias.x, acc[1] + bias.y);
            *(float2*)&out[(size_t)(row + 8)*CC + col] =
                make_float2(acc[2] + bias.x, acc[3] + bias.y);
        }
    }
}

// ---------------------------------------------------------------------------
// Launch
// ---------------------------------------------------------------------------
extern "C" void kernel_launch(void* const* d_in, const int* in_sizes, int n_in,
                              void* d_out, int out_size) {
    const float* x  = (const float*)d_in[0];
    const float* Wq = (const float*)d_in[1];
    const float* Wk = (const float*)d_in[2];
    const float* Wv = (const float*)d_in[3];
    const float* Wp = (const float*)d_in[4];
    const float* bp = (const float*)d_in[5];
    float* out = (float*)d_out;

    const int qkv_smem  = 8320 * 4;     // 33280 B
    const int attn_smem = 44224 * 4;    // 176896 B

    cudaFuncSetAttribute(qkv_kernel,  cudaFuncAttributeMaxDynamicSharedMemorySize, qkv_smem);
    cudaFuncSetAttribute(attn_kernel, cudaFuncAttributeMaxDynamicSharedMemorySize, attn_smem);

    prep_kernel<<<256, 256>>>(Wq, Wk, Wv, Wp);
    qkv_kernel<<<MM/64, 256, qkv_smem>>>(x);
    attn_kernel<<<256, 256, attn_smem>>>(out, bp);
}